// round 9
// baseline (speedup 1.0000x reference)
#include <cuda_runtime.h>

// Problem constants
#define BS   64
#define SEQ  512
#define H    768
#define TT   64   // topic count per batch
#define KK   64   // token count per batch

#define THREADS   256
#define CHUNK     16          // rows per block (block y==0 has 17: +cls)
#define NROWS_MAX 17

// Dynamic smem layout (floats):
//   sA  [4*768]  : A-vector slots {prim_c0, prim_c1, cls_c0, cls_c1}
//   sD0 [768]    : concat(src_emb, tgt_emb) for this batch
//   sH  [17*768] : staged hidden rows
#define SMEM_FLOATS (4 * H + H + NROWS_MAX * H)
#define SMEM_BYTES  (SMEM_FLOATS * 4)

// ---------------------------------------------------------------------------
// Single fused kernel. grid = (BS, 8):
//   y in [0,3]: topic quarter y*16..y*16+15  (y==0 additionally owns the cls row)
//   y in [4,7]: token quarter (y-4)*16..
// Per block: gather its 16-17 hidden rows via cp.async (DRAM, in flight early),
// compute its own A-vector pair(s) from W while the gather flies (L2-resident W),
// then warp-per-row smem dots + fused bias/mask/softmax epilogue.
// ---------------------------------------------------------------------------
__global__ void __launch_bounds__(THREADS) fused_kernel(
    const float* __restrict__ hidden,     // [BS, SEQ, H]
    const float* __restrict__ Wsrc,       // [862, 384]
    const float* __restrict__ Wtgt,       // [862, 384]
    const float* __restrict__ Wcls,       // [2, 6144]
    const float* __restrict__ Wtopic,     // [2, 6144]
    const float* __restrict__ Wtoken,     // [2, 6144]
    const float* __restrict__ b_cls,      // [2]
    const float* __restrict__ b_topic,    // [2]
    const float* __restrict__ b_token,    // [2]
    const int*   __restrict__ src_ids,    // [BS]
    const int*   __restrict__ tgt_ids,    // [BS]
    const int*   __restrict__ topic_inds, // [BS, TT]
    const float* __restrict__ topic_mask, // [BS, TT]
    const int*   __restrict__ token_inds, // [BS, KK]
    const float* __restrict__ token_mask, // [BS, KK]
    float* __restrict__ out)              // [128 | 8192 | 8192]
{
    const int b    = blockIdx.x;
    const int y    = blockIdx.y;
    const int tid  = threadIdx.x;
    const int warp = tid >> 5;
    const int lane = tid & 31;

    extern __shared__ float smem[];
    float* sA  = smem;              // 4*768
    float* sD0 = smem + 4 * H;      // 768
    float* sH  = smem + 5 * H;      // 17*768
    __shared__ int   sIdx[NROWS_MAX];
    __shared__ float sMask[NROWS_MAX];

    const bool is_topic = (y < 4);
    const int  qoff  = (y & 3) * CHUNK;           // row offset within type
    const int  nrows = (y == 0) ? CHUNK + 1 : CHUNK;

    // ---- Phase 1: indices, masks, d0 -------------------------------------
    if (tid < nrows) {
        int idx; float mk;
        if (y == 0 && tid == CHUNK) {             // cls row
            idx = 0; mk = 1.f;
        } else if (is_topic) {
            idx = topic_inds[b * TT + qoff + tid];
            mk  = topic_mask[b * TT + qoff + tid];
        } else {
            idx = token_inds[b * KK + qoff + tid];
            mk  = token_mask[b * KK + qoff + tid];
        }
        sIdx[tid]  = idx;
        sMask[tid] = mk;
    }
    {
        const float* __restrict__ s = Wsrc + (size_t)src_ids[b] * 384;
        const float* __restrict__ t = Wtgt + (size_t)tgt_ids[b] * 384;
        for (int i = tid; i < 384; i += THREADS) {
            sD0[i]       = s[i];
            sD0[384 + i] = t[i];
        }
    }
    __syncthreads();

    // ---- Phase 2: fire the DRAM gather (cp.async, no register cost) ------
    const float* __restrict__ hb = hidden + (size_t)b * SEQ * H;
    for (int lr = warp; lr < nrows; lr += 8) {
        const float4* __restrict__ src =
            (const float4*)(hb + (size_t)sIdx[lr] * H) + lane;
        unsigned dst = (unsigned)__cvta_generic_to_shared(sH + lr * H)
                       + (unsigned)(lane * 16);
#pragma unroll
        for (int k = 0; k < 6; k++) {
            asm volatile("cp.async.cg.shared.global [%0], [%1], 16;\n"
                         :: "r"(dst + (unsigned)(k * 512)), "l"(src + k * 32));
        }
    }
    asm volatile("cp.async.commit_group;\n");

    // ---- Phase 3: compute A vectors (overlaps the gather) ----------------
    // slot 0/1: primary type pair; slot 2/3 (y==0 only): cls pair
    {
        const float* __restrict__ Wprim = is_topic ? Wtopic : Wtoken;
        const int nvec = (y == 0) ? 4 : 2;
        for (int v = 0; v < nvec; v++) {
            const float* __restrict__ Wb =
                (v < 2 ? Wprim : Wcls) + (v & 1) * 6144;
            for (int e = tid; e < H; e += THREADS) {
                const int g = e >> 3;
                const int j = e & 7;
                const float* __restrict__ W = Wb + g * 64 + j;
                const float* __restrict__ d = sD0 + g * 8;
                float acc = 0.f;
#pragma unroll
                for (int i = 0; i < 8; i++)
                    acc = fmaf(d[i], W[i * 8], acc);
                sA[v * H + e] = acc;
            }
        }
    }
    __syncthreads();   // sA visible to all warps

    // ---- Phase 4: wait for own staged rows -------------------------------
    // Each lane below reads exactly the float4s it staged itself, and sA was
    // synced above, so wait_group 0 alone is sufficient.
    asm volatile("cp.async.wait_group 0;\n");

    // ---- Phase 5: warp-per-row dots + epilogue ---------------------------
    float pb0, pb1;
    if (is_topic) { pb0 = b_topic[0]; pb1 = b_topic[1]; }
    else          { pb0 = b_token[0]; pb1 = b_token[1]; }

    for (int lr = warp; lr < nrows; lr += 8) {
        const bool is_cls = (y == 0) && (lr == CHUNK);
        const float4* __restrict__ h4 = (const float4*)(sH + lr * H);
        const float4* __restrict__ a0 =
            (const float4*)(sA + (is_cls ? 2 * H : 0));
        const float4* __restrict__ a1 = a0 + (H / 4);

        float acc0 = 0.f, acc1 = 0.f;
#pragma unroll
        for (int k = 0; k < 6; k++) {
            const int p = lane + k * 32;
            const float4 h = h4[p];
            const float4 x = a0[p];
            const float4 z = a1[p];
            acc0 = fmaf(h.x, x.x, fmaf(h.y, x.y, fmaf(h.z, x.z, fmaf(h.w, x.w, acc0))));
            acc1 = fmaf(h.x, z.x, fmaf(h.y, z.y, fmaf(h.z, z.z, fmaf(h.w, z.w, acc1))));
        }
#pragma unroll
        for (int o = 16; o; o >>= 1) {
            acc0 += __shfl_xor_sync(0xFFFFFFFFu, acc0, o);
            acc1 += __shfl_xor_sync(0xFFFFFFFFu, acc1, o);
        }

        if (lane == 0) {
            const float mask  = sMask[lr];
            const float bias0 = is_cls ? b_cls[0] : pb0;
            const float bias1 = is_cls ? b_cls[1] : pb1;
            const float x0 = fmaf(mask, acc0, bias0);
            const float x1 = fmaf(mask, acc1, bias1);

            float* outp;
            bool do_softmax;
            if (is_cls) {
                outp = out + b * 2;
                do_softmax = true;
            } else if (is_topic) {
                outp = out + 128 + (b * TT + qoff + lr) * 2;
                do_softmax = true;
            } else {
                outp = out + 128 + BS * TT * 2 + (b * KK + qoff + lr) * 2;
                do_softmax = false;
            }

            if (do_softmax) {
                const float mx = fmaxf(x0, x1);
                const float e0 = __expf(x0 - mx);
                const float e1 = __expf(x1 - mx);
                const float inv = 1.f / (e0 + e1);
                outp[0] = e0 * inv;
                outp[1] = e1 * inv;
            } else {
                outp[0] = x0;
                outp[1] = x1;
            }
        }
    }
}

// ---------------------------------------------------------------------------
// Launch: single kernel, dynamic smem (66 KB -> 3 blocks/SM).
// ---------------------------------------------------------------------------
extern "C" void kernel_launch(void* const* d_in, const int* in_sizes, int n_in,
                              void* d_out, int out_size)
{
    const float* hidden     = (const float*)d_in[0];   // [64,512,768]
    const float* Wsrc       = (const float*)d_in[1];   // [862,384]
    const float* Wtgt       = (const float*)d_in[2];   // [862,384]
    const float* W_cls      = (const float*)d_in[3];   // [2,6144]
    const float* b_cls      = (const float*)d_in[4];   // [2]
    const float* W_topic    = (const float*)d_in[5];   // [2,6144]
    const float* b_topic    = (const float*)d_in[6];   // [2]
    const float* W_token    = (const float*)d_in[7];   // [2,6144]
    const float* b_token    = (const float*)d_in[8];   // [2]
    const int*   source_ids = (const int*)d_in[9];     // [64]
    const int*   target_ids = (const int*)d_in[10];    // [64]
    // d_in[11] ent_inds, d_in[12] ent_mask: unused by reference outputs
    const int*   topic_inds = (const int*)d_in[13];    // [64,64]
    const float* topic_mask = (const float*)d_in[14];  // [64,64]
    const int*   token_inds = (const int*)d_in[15];    // [64,64]
    const float* token_mask = (const float*)d_in[16];  // [64,64]

    float* out = (float*)d_out;

    cudaFuncSetAttribute(fused_kernel,
                         cudaFuncAttributeMaxDynamicSharedMemorySize,
                         SMEM_BYTES);

    fused_kernel<<<dim3(BS, 8), THREADS, SMEM_BYTES>>>(
        hidden, Wsrc, Wtgt, W_cls, W_topic, W_token,
        b_cls, b_topic, b_token,
        source_ids, target_ids,
        topic_inds, topic_mask, token_inds, token_mask, out);
}

// round 10
// speedup vs baseline: 1.2056x; 1.2056x over previous
#include <cuda_runtime.h>

// Problem constants
#define BS   64
#define SEQ  512
#define H    768
#define TT   64   // topic count per batch
#define KK   64   // token count per batch

#define THREADS   256
#define CHUNK     16          // rows per block (block y==0 has 17: +cls)
#define NROWS_MAX 17

// g_A[b][m][p]: m in {cls_c0, cls_c1, topic_c0, topic_c1, token_c0, token_c1}
__device__ float4 g_A4[BS * 6 * H / 4];

// Dynamic smem (floats): sA[4*768] | sH[17*768]  -> 64512 B
#define SMEM_BYTES ((4 * H + NROWS_MAX * H) * 4)

// ---------------------------------------------------------------------------
// Kernel 1: build the 6 factored A vectors per batch.
// grid (BS, 6): block (b, m) computes A[b][m][0..767].
// ---------------------------------------------------------------------------
__global__ void __launch_bounds__(128) build_A_kernel(
    const float* __restrict__ Wsrc,   // [862, 384]
    const float* __restrict__ Wtgt,   // [862, 384]
    const float* __restrict__ Wcls,   // [2, 6144]
    const float* __restrict__ Wtopic, // [2, 6144]
    const float* __restrict__ Wtoken, // [2, 6144]
    const int*   __restrict__ src_ids,
    const int*   __restrict__ tgt_ids)
{
    const int b   = blockIdx.x;
    const int m   = blockIdx.y;      // 0..5
    const int tid = threadIdx.x;

    __shared__ float d0[H];  // concat(src_emb, tgt_emb)

    const float* __restrict__ s = Wsrc + (size_t)src_ids[b] * 384;
    const float* __restrict__ t = Wtgt + (size_t)tgt_ids[b] * 384;
    for (int i = tid; i < 384; i += blockDim.x) {
        d0[i]       = s[i];
        d0[384 + i] = t[i];
    }
    __syncthreads();

    const int w = m >> 1;
    const int c = m & 1;
    const float* __restrict__ Wbase =
        (w == 0 ? Wcls : (w == 1 ? Wtopic : Wtoken)) + c * 6144;

    float* __restrict__ Ab = ((float*)g_A4) + ((size_t)b * 6 + m) * H;

#pragma unroll
    for (int e = tid; e < H; e += 128) {
        const int g = e >> 3;
        const int j = e & 7;
        const float* __restrict__ W = Wbase + g * 64 + j;
        const float* __restrict__ d = d0 + g * 8;
        float acc = 0.f;
#pragma unroll
        for (int i = 0; i < 8; i++)
            acc = fmaf(d[i], W[i * 8], acc);
        Ab[e] = acc;
    }

#if __CUDA_ARCH__ >= 900
    cudaTriggerProgrammaticLaunchCompletion();
#endif
}

// ---------------------------------------------------------------------------
// Kernel 2: grid (BS, 8), 256 thr. y<4: topic quarter; y>=4: token quarter;
// y==0 also owns the cls row. Per block:
//   Phase 1 (pre-dependency): indices + cp.async gather of its 16-17 rows.
//   Phase 2 (post cudaGridDependencySynchronize): cp.async its A pair(s)
//     from g_A (6-12 KB, L2), one commit+wait, syncthreads.
//   Phase 3: 2 rows per warp, smem dots + fused epilogue.
// ---------------------------------------------------------------------------
__global__ void __launch_bounds__(THREADS) rows_kernel(
    const float* __restrict__ hidden,     // [BS, SEQ, H]
    const float* __restrict__ b_cls,      // [2]
    const float* __restrict__ b_topic,    // [2]
    const float* __restrict__ b_token,    // [2]
    const int*   __restrict__ topic_inds, // [BS, TT]
    const float* __restrict__ topic_mask, // [BS, TT]
    const int*   __restrict__ token_inds, // [BS, KK]
    const float* __restrict__ token_mask, // [BS, KK]
    float* __restrict__ out)              // [128 | 8192 | 8192]
{
    const int b    = blockIdx.x;
    const int y    = blockIdx.y;
    const int tid  = threadIdx.x;
    const int warp = tid >> 5;
    const int lane = tid & 31;

    extern __shared__ float smem[];
    float* sA = smem;           // 4*768 : {prim_c0, prim_c1, cls_c0, cls_c1}
    float* sH = smem + 4 * H;   // 17*768
    __shared__ int   sIdx[NROWS_MAX];
    __shared__ float sMask[NROWS_MAX];

    const bool is_topic = (y < 4);
    const int  qoff  = (y & 3) * CHUNK;
    const int  nrows = (y == 0) ? CHUNK + 1 : CHUNK;

    // ---- Phase 1a: indices + masks (the only pre-gather dependency) ------
    if (tid < nrows) {
        int idx; float mk;
        if (y == 0 && tid == CHUNK) {             // cls row
            idx = 0; mk = 1.f;
        } else if (is_topic) {
            idx = topic_inds[b * TT + qoff + tid];
            mk  = topic_mask[b * TT + qoff + tid];
        } else {
            idx = token_inds[b * KK + qoff + tid];
            mk  = token_mask[b * KK + qoff + tid];
        }
        sIdx[tid]  = idx;
        sMask[tid] = mk;
    }
    __syncthreads();

    // ---- Phase 1b: fire the DRAM gather (cp.async) ------------------------
    const float* __restrict__ hb = hidden + (size_t)b * SEQ * H;
    for (int lr = warp; lr < nrows; lr += 8) {
        const float4* __restrict__ src =
            (const float4*)(hb + (size_t)sIdx[lr] * H) + lane;
        unsigned dst = (unsigned)__cvta_generic_to_shared(sH + lr * H)
                       + (unsigned)(lane * 16);
#pragma unroll
        for (int k = 0; k < 6; k++) {
            asm volatile("cp.async.cg.shared.global [%0], [%1], 16;\n"
                         :: "r"(dst + (unsigned)(k * 512)), "l"(src + k * 32));
        }
    }

    // ---- Phase 2: dependency point, then stage A pair(s) from g_A --------
#if __CUDA_ARCH__ >= 900
    cudaGridDependencySynchronize();
#endif
    {
        const int m0 = is_topic ? 2 : 4;
        const float4* __restrict__ Ap = g_A4 + ((size_t)b * 6 + m0) * (H / 4);
        for (int e = tid; e < 2 * H / 4; e += THREADS) {
            unsigned d = (unsigned)__cvta_generic_to_shared(sA) + e * 16u;
            asm volatile("cp.async.cg.shared.global [%0], [%1], 16;\n"
                         :: "r"(d), "l"(Ap + e));
        }
        if (y == 0) {   // cls pair into slots 2/3
            const float4* __restrict__ Ac = g_A4 + (size_t)b * 6 * (H / 4);
            for (int e = tid; e < 2 * H / 4; e += THREADS) {
                unsigned d = (unsigned)__cvta_generic_to_shared(sA + 2 * H) + e * 16u;
                asm volatile("cp.async.cg.shared.global [%0], [%1], 16;\n"
                             :: "r"(d), "l"(Ac + e));
            }
        }
    }
    asm volatile("cp.async.commit_group;\n");
    asm volatile("cp.async.wait_group 0;\n");
    __syncthreads();

    // ---- Phase 3: warp-per-row dots + epilogue ---------------------------
    float pb0, pb1;
    if (is_topic) { pb0 = b_topic[0]; pb1 = b_topic[1]; }
    else          { pb0 = b_token[0]; pb1 = b_token[1]; }

    for (int lr = warp; lr < nrows; lr += 8) {
        const bool is_cls = (y == 0) && (lr == CHUNK);
        const float4* __restrict__ h4 = (const float4*)(sH + lr * H);
        const float4* __restrict__ a0 =
            (const float4*)(sA + (is_cls ? 2 * H : 0));
        const float4* __restrict__ a1 = a0 + (H / 4);

        float acc0 = 0.f, acc1 = 0.f;
#pragma unroll
        for (int k = 0; k < 6; k++) {
            const int p = lane + k * 32;
            const float4 h = h4[p];
            const float4 x = a0[p];
            const float4 z = a1[p];
            acc0 = fmaf(h.x, x.x, fmaf(h.y, x.y, fmaf(h.z, x.z, fmaf(h.w, x.w, acc0))));
            acc1 = fmaf(h.x, z.x, fmaf(h.y, z.y, fmaf(h.z, z.z, fmaf(h.w, z.w, acc1))));
        }
#pragma unroll
        for (int o = 16; o; o >>= 1) {
            acc0 += __shfl_xor_sync(0xFFFFFFFFu, acc0, o);
            acc1 += __shfl_xor_sync(0xFFFFFFFFu, acc1, o);
        }

        if (lane == 0) {
            const float mask  = sMask[lr];
            const float bias0 = is_cls ? b_cls[0] : pb0;
            const float bias1 = is_cls ? b_cls[1] : pb1;
            const float x0 = fmaf(mask, acc0, bias0);
            const float x1 = fmaf(mask, acc1, bias1);

            float* outp;
            bool do_softmax;
            if (is_cls) {
                outp = out + b * 2;
                do_softmax = true;
            } else if (is_topic) {
                outp = out + 128 + (b * TT + qoff + lr) * 2;
                do_softmax = true;
            } else {
                outp = out + 128 + BS * TT * 2 + (b * KK + qoff + lr) * 2;
                do_softmax = false;
            }

            if (do_softmax) {
                const float mx = fmaxf(x0, x1);
                const float e0 = __expf(x0 - mx);
                const float e1 = __expf(x1 - mx);
                const float inv = 1.f / (e0 + e1);
                outp[0] = e0 * inv;
                outp[1] = e1 * inv;
            } else {
                outp[0] = x0;
                outp[1] = x1;
            }
        }
    }
}

// ---------------------------------------------------------------------------
// Launch: build_A, then rows_kernel under PDL (gather prologue overlaps).
// ---------------------------------------------------------------------------
extern "C" void kernel_launch(void* const* d_in, const int* in_sizes, int n_in,
                              void* d_out, int out_size)
{
    const float* hidden     = (const float*)d_in[0];   // [64,512,768]
    const float* Wsrc       = (const float*)d_in[1];   // [862,384]
    const float* Wtgt       = (const float*)d_in[2];   // [862,384]
    const float* W_cls      = (const float*)d_in[3];   // [2,6144]
    const float* b_cls      = (const float*)d_in[4];   // [2]
    const float* W_topic    = (const float*)d_in[5];   // [2,6144]
    const float* b_topic    = (const float*)d_in[6];   // [2]
    const float* W_token    = (const float*)d_in[7];   // [2,6144]
    const float* b_token    = (const float*)d_in[8];   // [2]
    const int*   source_ids = (const int*)d_in[9];     // [64]
    const int*   target_ids = (const int*)d_in[10];    // [64]
    // d_in[11] ent_inds, d_in[12] ent_mask: unused by reference outputs
    const int*   topic_inds = (const int*)d_in[13];    // [64,64]
    const float* topic_mask = (const float*)d_in[14];  // [64,64]
    const int*   token_inds = (const int*)d_in[15];    // [64,64]
    const float* token_mask = (const float*)d_in[16];  // [64,64]

    float* out = (float*)d_out;

    build_A_kernel<<<dim3(BS, 6), 128>>>(Wsrc, Wtgt, W_cls, W_topic, W_token,
                                         source_ids, target_ids);

    cudaFuncSetAttribute(rows_kernel,
                         cudaFuncAttributeMaxDynamicSharedMemorySize,
                         SMEM_BYTES);

    cudaLaunchConfig_t cfg = {};
    cfg.gridDim          = dim3(BS, 8);
    cfg.blockDim         = dim3(THREADS);
    cfg.dynamicSmemBytes = SMEM_BYTES;
    cfg.stream           = 0;
    cudaLaunchAttribute attr[1];
    attr[0].id = cudaLaunchAttributeProgrammaticStreamSerialization;
    attr[0].val.programmaticStreamSerializationAllowed = 1;
    cfg.attrs    = attr;
    cfg.numAttrs = 1;

    cudaLaunchKernelEx(&cfg, rows_kernel, hidden, b_cls, b_topic, b_token,
                       topic_inds, topic_mask, token_inds, token_mask, out);
}

// round 11
// speedup vs baseline: 1.3665x; 1.1335x over previous
#include <cuda_runtime.h>

// Problem constants
#define BS   64
#define SEQ  512
#define H    768
#define TT   64   // topic count per batch
#define KK   64   // token count per batch

#define THREADS 512
#define CHUNK   16

// ---------------------------------------------------------------------------
// Single fused kernel. grid = (BS, 9), 512 threads:
//   y in [0,3]: topic rows y*16..y*16+15
//   y in [4,7]: token rows (y-4)*16..
//   y == 8   : the cls row only
// Per block:
//   1. indices + d0 (embedding concat) -> smem, sync
//   2. warp-per-row: issue 6 LDG.128 of the hidden row into REGISTERS
//      (fires the DRAM gather immediately, no consumer)
//   3. compute this block's single A-vector pair from W (L2) + d0 — its W
//      loads drain behind the h wavefronts, i.e. for free
//   4. one barrier, then dot(h_regs, sA) + shfl reduce + fused epilogue
// ---------------------------------------------------------------------------
__global__ void __launch_bounds__(THREADS) fused_kernel(
    const float* __restrict__ hidden,     // [BS, SEQ, H]
    const float* __restrict__ Wsrc,       // [862, 384]
    const float* __restrict__ Wtgt,       // [862, 384]
    const float* __restrict__ Wcls,       // [2, 6144]
    const float* __restrict__ Wtopic,     // [2, 6144]
    const float* __restrict__ Wtoken,     // [2, 6144]
    const float* __restrict__ b_cls,      // [2]
    const float* __restrict__ b_topic,    // [2]
    const float* __restrict__ b_token,    // [2]
    const int*   __restrict__ src_ids,    // [BS]
    const int*   __restrict__ tgt_ids,    // [BS]
    const int*   __restrict__ topic_inds, // [BS, TT]
    const float* __restrict__ topic_mask, // [BS, TT]
    const int*   __restrict__ token_inds, // [BS, KK]
    const float* __restrict__ token_mask, // [BS, KK]
    float* __restrict__ out)              // [128 | 8192 | 8192]
{
    const int b    = blockIdx.x;
    const int y    = blockIdx.y;           // 0..8
    const int tid  = threadIdx.x;
    const int warp = tid >> 5;
    const int lane = tid & 31;

    __shared__ float sD0[H];               // concat(src_emb, tgt_emb)
    __shared__ float sA[2 * H];            // this block's A pair {c0, c1}
    __shared__ int   sIdx[CHUNK];
    __shared__ float sMask[CHUNK];

    const bool is_cls   = (y == 8);
    const bool is_topic = (y < 4);
    const int  qoff     = (y & 3) * CHUNK;
    const int  nrows    = is_cls ? 1 : CHUNK;

    // ---- Phase 1: indices/masks + d0 -------------------------------------
    if (tid < nrows) {
        int idx; float mk;
        if (is_cls) {
            idx = 0; mk = 1.f;
        } else if (is_topic) {
            idx = topic_inds[b * TT + qoff + tid];
            mk  = topic_mask[b * TT + qoff + tid];
        } else {
            idx = token_inds[b * KK + qoff + tid];
            mk  = token_mask[b * KK + qoff + tid];
        }
        sIdx[tid]  = idx;
        sMask[tid] = mk;
    }
    {
        const float* __restrict__ s = Wsrc + (size_t)src_ids[b] * 384;
        const float* __restrict__ t = Wtgt + (size_t)tgt_ids[b] * 384;
        for (int i = tid; i < 384; i += THREADS) {
            sD0[i]       = s[i];
            sD0[384 + i] = t[i];
        }
    }
    __syncthreads();

    // ---- Phase 2: fire the DRAM gather into registers --------------------
    const bool active = (warp < nrows);
    float4 h0, h1, h2, h3, h4v, h5;
    if (active) {
        const float4* __restrict__ src =
            (const float4*)(hidden + ((size_t)b * SEQ + sIdx[warp]) * H) + lane;
        h0  = src[0];
        h1  = src[32];
        h2  = src[64];
        h3  = src[96];
        h4v = src[128];
        h5  = src[160];
    }

    // ---- Phase 3: compute this block's A pair (W loads hide behind h) ----
    {
        const float* __restrict__ Wb =
            is_cls ? Wcls : (is_topic ? Wtopic : Wtoken);
        for (int e = tid; e < 2 * H; e += THREADS) {
            const int v = (e >= H) ? 1 : 0;
            const int p = e - v * H;
            const int g = p >> 3;
            const int j = p & 7;
            const float* __restrict__ W = Wb + v * 6144 + g * 64 + j;
            const float* __restrict__ d = sD0 + g * 8;
            float acc = 0.f;
#pragma unroll
            for (int i = 0; i < 8; i++)
                acc = fmaf(d[i], W[i * 8], acc);
            sA[e] = acc;
        }
    }
    __syncthreads();

    // ---- Phase 4: dot + reduce + epilogue --------------------------------
    if (active) {
        const float4* __restrict__ a0 = (const float4*)sA;
        const float4* __restrict__ a1 = a0 + (H / 4);

        float acc0 = 0.f, acc1 = 0.f;
        {
            float4 h, x, z;
#define DOT_STEP(HV, OFF)                                                        \
            h = (HV); x = a0[lane + (OFF)]; z = a1[lane + (OFF)];                \
            acc0 = fmaf(h.x, x.x, fmaf(h.y, x.y, fmaf(h.z, x.z, fmaf(h.w, x.w, acc0)))); \
            acc1 = fmaf(h.x, z.x, fmaf(h.y, z.y, fmaf(h.z, z.z, fmaf(h.w, z.w, acc1))));
            DOT_STEP(h0,   0)
            DOT_STEP(h1,  32)
            DOT_STEP(h2,  64)
            DOT_STEP(h3,  96)
            DOT_STEP(h4v, 128)
            DOT_STEP(h5, 160)
#undef DOT_STEP
        }
#pragma unroll
        for (int o = 16; o; o >>= 1) {
            acc0 += __shfl_xor_sync(0xFFFFFFFFu, acc0, o);
            acc1 += __shfl_xor_sync(0xFFFFFFFFu, acc1, o);
        }

        if (lane == 0) {
            const float mask = sMask[warp];
            float bias0, bias1;
            float* outp;
            bool do_softmax;
            if (is_cls) {
                bias0 = b_cls[0]; bias1 = b_cls[1];
                outp = out + b * 2;
                do_softmax = true;
            } else if (is_topic) {
                bias0 = b_topic[0]; bias1 = b_topic[1];
                outp = out + 128 + (b * TT + qoff + warp) * 2;
                do_softmax = true;
            } else {
                bias0 = b_token[0]; bias1 = b_token[1];
                outp = out + 128 + BS * TT * 2 + (b * KK + qoff + warp) * 2;
                do_softmax = false;
            }

            const float x0 = fmaf(mask, acc0, bias0);
            const float x1 = fmaf(mask, acc1, bias1);
            if (do_softmax) {
                const float mx = fmaxf(x0, x1);
                const float e0 = __expf(x0 - mx);
                const float e1 = __expf(x1 - mx);
                const float inv = 1.f / (e0 + e1);
                outp[0] = e0 * inv;
                outp[1] = e1 * inv;
            } else {
                outp[0] = x0;
                outp[1] = x1;
            }
        }
    }
}

// ---------------------------------------------------------------------------
// Launch: one kernel, static smem (~9 KB), grid (64, 9).
// ---------------------------------------------------------------------------
extern "C" void kernel_launch(void* const* d_in, const int* in_sizes, int n_in,
                              void* d_out, int out_size)
{
    const float* hidden     = (const float*)d_in[0];   // [64,512,768]
    const float* Wsrc       = (const float*)d_in[1];   // [862,384]
    const float* Wtgt       = (const float*)d_in[2];   // [862,384]
    const float* W_cls      = (const float*)d_in[3];   // [2,6144]
    const float* b_cls      = (const float*)d_in[4];   // [2]
    const float* W_topic    = (const float*)d_in[5];   // [2,6144]
    const float* b_topic    = (const float*)d_in[6];   // [2]
    const float* W_token    = (const float*)d_in[7];   // [2,6144]
    const float* b_token    = (const float*)d_in[8];   // [2]
    const int*   source_ids = (const int*)d_in[9];     // [64]
    const int*   target_ids = (const int*)d_in[10];    // [64]
    // d_in[11] ent_inds, d_in[12] ent_mask: unused by reference outputs
    const int*   topic_inds = (const int*)d_in[13];    // [64,64]
    const float* topic_mask = (const float*)d_in[14];  // [64,64]
    const int*   token_inds = (const int*)d_in[15];    // [64,64]
    const float* token_mask = (const float*)d_in[16];  // [64,64]

    float* out = (float*)d_out;

    fused_kernel<<<dim3(BS, 9), THREADS>>>(
        hidden, Wsrc, Wtgt, W_cls, W_topic, W_token,
        b_cls, b_topic, b_token,
        source_ids, target_ids,
        topic_inds, topic_mask, token_inds, token_mask, out);
}

// round 12
// speedup vs baseline: 1.5770x; 1.1540x over previous
#include <cuda_runtime.h>

// Problem constants
#define BS   64
#define SEQ  512
#define H    768
#define TT   64   // topic count per batch
#define KK   64   // token count per batch

#define RPB      8            // rows per block in rows_kernel
#define RTHREADS 256

// g_A[b][m][p]: m in {cls_c0, cls_c1, topic_c0, topic_c1, token_c0, token_c1}
__device__ float4 g_A4[BS * 6 * H / 4];

// rows_kernel dynamic smem: sA[2*768] + sH[8*768] floats = 30720 B
#define RSMEM_BYTES ((2 * H + RPB * H) * 4)

// ---------------------------------------------------------------------------
// Kernel 1: build the 6 factored A vectors per batch — smem-staged W.
// grid (BS, 6): block (b, m). Coalesced float4 loads of the whole W row and
// the two embedding rows into smem (one overlapped latency exposure), then
// 8-FMA-per-output from smem.
// ---------------------------------------------------------------------------
__global__ void __launch_bounds__(256) build_A_kernel(
    const float* __restrict__ Wsrc,   // [862, 384]
    const float* __restrict__ Wtgt,   // [862, 384]
    const float* __restrict__ Wcls,   // [2, 6144]
    const float* __restrict__ Wtopic, // [2, 6144]
    const float* __restrict__ Wtoken, // [2, 6144]
    const int*   __restrict__ src_ids,
    const int*   __restrict__ tgt_ids)
{
    const int b   = blockIdx.x;
    const int m   = blockIdx.y;      // 0..5
    const int tid = threadIdx.x;

    __shared__ float sW[6144];       // 24 KB: W[m-half] row
    __shared__ float d0[H];          // 3 KB

    const int w = m >> 1;
    const int c = m & 1;
    const float4* __restrict__ Wb = (const float4*)(
        (w == 0 ? Wcls : (w == 1 ? Wtopic : Wtoken)) + c * 6144);

    // Coalesced staging: 1536 float4 of W + 192 float4 of embeddings.
    {
        float4* sW4 = (float4*)sW;
#pragma unroll
        for (int e = tid; e < 1536; e += 256)
            sW4[e] = Wb[e];

        const float4* __restrict__ s =
            (const float4*)(Wsrc + (size_t)src_ids[b] * 384);
        const float4* __restrict__ t =
            (const float4*)(Wtgt + (size_t)tgt_ids[b] * 384);
        float4* d04 = (float4*)d0;
        if (tid < 96)       d04[tid]      = s[tid];
        else if (tid < 192) d04[tid - 96 + 96] = t[tid - 96];
    }
    __syncthreads();

    float* __restrict__ Ab = ((float*)g_A4) + ((size_t)b * 6 + m) * H;

#pragma unroll
    for (int e = tid; e < H; e += 256) {
        const int g = e >> 3;
        const int j = e & 7;
        const float* __restrict__ Wp = sW + g * 64 + j;
        const float* __restrict__ d  = d0 + g * 8;
        float acc = 0.f;
#pragma unroll
        for (int i = 0; i < 8; i++)
            acc = fmaf(d[i], Wp[i * 8], acc);
        Ab[e] = acc;
    }

#if __CUDA_ARCH__ >= 900
    cudaTriggerProgrammaticLaunchCompletion();
#endif
}

// ---------------------------------------------------------------------------
// Kernel 2: grid (BS, 17), 256 thr, warp-per-row, type-split blocks:
//   y in [0,7]  : topic rows y*8 .. y*8+7
//   y in [8,15] : token rows (y-8)*8 ..
//   y == 16     : cls row
// Phase 1 (pre-dependency): indices + cp.async gather of 8 rows (DRAM).
// Phase 2 (post-dependency): cp.async ONE A pair (6 KB, L2), commit+wait+sync.
// Phase 3: smem dots + fused epilogue.
// ---------------------------------------------------------------------------
__global__ void __launch_bounds__(RTHREADS) rows_kernel(
    const float* __restrict__ hidden,     // [BS, SEQ, H]
    const float* __restrict__ b_cls,      // [2]
    const float* __restrict__ b_topic,    // [2]
    const float* __restrict__ b_token,    // [2]
    const int*   __restrict__ topic_inds, // [BS, TT]
    const float* __restrict__ topic_mask, // [BS, TT]
    const int*   __restrict__ token_inds, // [BS, KK]
    const float* __restrict__ token_mask, // [BS, KK]
    float* __restrict__ out)              // [128 | 8192 | 8192]
{
    const int b    = blockIdx.x;
    const int y    = blockIdx.y;          // 0..16
    const int tid  = threadIdx.x;
    const int warp = tid >> 5;
    const int lane = tid & 31;

    extern __shared__ float smem[];
    float* sA = smem;           // 2*768
    float* sH = smem + 2 * H;   // 8*768
    __shared__ int   sIdx[RPB];
    __shared__ float sMask[RPB];

    const bool is_cls   = (y == 16);
    const bool is_topic = (y < 8);
    const int  qoff     = (y & 7) * RPB;
    const int  nrows    = is_cls ? 1 : RPB;

    // ---- Phase 1a: indices + masks ---------------------------------------
    if (tid < nrows) {
        int idx; float mk;
        if (is_cls) {
            idx = 0; mk = 1.f;
        } else if (is_topic) {
            idx = topic_inds[b * TT + qoff + tid];
            mk  = topic_mask[b * TT + qoff + tid];
        } else {
            idx = token_inds[b * KK + qoff + tid];
            mk  = token_mask[b * KK + qoff + tid];
        }
        sIdx[tid]  = idx;
        sMask[tid] = mk;
    }
    __syncthreads();

    // ---- Phase 1b: fire the DRAM gather (cp.async, warp-per-row) ----------
    if (warp < nrows) {
        const float4* __restrict__ src =
            (const float4*)(hidden + ((size_t)b * SEQ + sIdx[warp]) * H) + lane;
        unsigned dst = (unsigned)__cvta_generic_to_shared(sH + warp * H)
                       + (unsigned)(lane * 16);
#pragma unroll
        for (int k = 0; k < 6; k++) {
            asm volatile("cp.async.cg.shared.global [%0], [%1], 16;\n"
                         :: "r"(dst + (unsigned)(k * 512)), "l"(src + k * 32));
        }
    }

    // ---- Phase 2: dependency point, then stage this block's A pair --------
#if __CUDA_ARCH__ >= 900
    cudaGridDependencySynchronize();
#endif
    {
        const int m0 = is_cls ? 0 : (is_topic ? 2 : 4);
        const float4* __restrict__ Ap = g_A4 + ((size_t)b * 6 + m0) * (H / 4);
        for (int e = tid; e < 2 * H / 4; e += RTHREADS) {
            unsigned d = (unsigned)__cvta_generic_to_shared(sA) + e * 16u;
            asm volatile("cp.async.cg.shared.global [%0], [%1], 16;\n"
                         :: "r"(d), "l"(Ap + e));
        }
    }
    asm volatile("cp.async.commit_group;\n");
    asm volatile("cp.async.wait_group 0;\n");
    __syncthreads();

    // ---- Phase 3: warp-per-row dot + epilogue ----------------------------
    if (warp < nrows) {
        const float4* __restrict__ h4 = (const float4*)(sH + warp * H);
        const float4* __restrict__ a0 = (const float4*)sA;
        const float4* __restrict__ a1 = a0 + (H / 4);

        float acc0 = 0.f, acc1 = 0.f;
#pragma unroll
        for (int k = 0; k < 6; k++) {
            const int p = lane + k * 32;
            const float4 h = h4[p];
            const float4 x = a0[p];
            const float4 z = a1[p];
            acc0 = fmaf(h.x, x.x, fmaf(h.y, x.y, fmaf(h.z, x.z, fmaf(h.w, x.w, acc0))));
            acc1 = fmaf(h.x, z.x, fmaf(h.y, z.y, fmaf(h.z, z.z, fmaf(h.w, z.w, acc1))));
        }
#pragma unroll
        for (int o = 16; o; o >>= 1) {
            acc0 += __shfl_xor_sync(0xFFFFFFFFu, acc0, o);
            acc1 += __shfl_xor_sync(0xFFFFFFFFu, acc1, o);
        }

        if (lane == 0) {
            const float mask = sMask[warp];
            float bias0, bias1;
            float* outp;
            bool do_softmax;
            if (is_cls) {
                bias0 = b_cls[0]; bias1 = b_cls[1];
                outp = out + b * 2;
                do_softmax = true;
            } else if (is_topic) {
                bias0 = b_topic[0]; bias1 = b_topic[1];
                outp = out + 128 + (b * TT + qoff + warp) * 2;
                do_softmax = true;
            } else {
                bias0 = b_token[0]; bias1 = b_token[1];
                outp = out + 128 + BS * TT * 2 + (b * KK + qoff + warp) * 2;
                do_softmax = false;
            }

            const float x0 = fmaf(mask, acc0, bias0);
            const float x1 = fmaf(mask, acc1, bias1);
            if (do_softmax) {
                const float mx = fmaxf(x0, x1);
                const float e0 = __expf(x0 - mx);
                const float e1 = __expf(x1 - mx);
                const float inv = 1.f / (e0 + e1);
                outp[0] = e0 * inv;
                outp[1] = e1 * inv;
            } else {
                outp[0] = x0;
                outp[1] = x1;
            }
        }
    }
}

// ---------------------------------------------------------------------------
// Launch: fast build_A, then rows_kernel under PDL.
// ---------------------------------------------------------------------------
extern "C" void kernel_launch(void* const* d_in, const int* in_sizes, int n_in,
                              void* d_out, int out_size)
{
    const float* hidden     = (const float*)d_in[0];   // [64,512,768]
    const float* Wsrc       = (const float*)d_in[1];   // [862,384]
    const float* Wtgt       = (const float*)d_in[2];   // [862,384]
    const float* W_cls      = (const float*)d_in[3];   // [2,6144]
    const float* b_cls      = (const float*)d_in[4];   // [2]
    const float* W_topic    = (const float*)d_in[5];   // [2,6144]
    const float* b_topic    = (const float*)d_in[6];   // [2]
    const float* W_token    = (const float*)d_in[7];   // [2,6144]
    const float* b_token    = (const float*)d_in[8];   // [2]
    const int*   source_ids = (const int*)d_in[9];     // [64]
    const int*   target_ids = (const int*)d_in[10];    // [64]
    // d_in[11] ent_inds, d_in[12] ent_mask: unused by reference outputs
    const int*   topic_inds = (const int*)d_in[13];    // [64,64]
    const float* topic_mask = (const float*)d_in[14];  // [64,64]
    const int*   token_inds = (const int*)d_in[15];    // [64,64]
    const float* token_mask = (const float*)d_in[16];  // [64,64]

    float* out = (float*)d_out;

    build_A_kernel<<<dim3(BS, 6), 256>>>(Wsrc, Wtgt, W_cls, W_topic, W_token,
                                         source_ids, target_ids);

    cudaFuncSetAttribute(rows_kernel,
                         cudaFuncAttributeMaxDynamicSharedMemorySize,
                         RSMEM_BYTES);

    cudaLaunchConfig_t cfg = {};
    cfg.gridDim          = dim3(BS, 17);
    cfg.blockDim         = dim3(RTHREADS);
    cfg.dynamicSmemBytes = RSMEM_BYTES;
    cfg.stream           = 0;
    cudaLaunchAttribute attr[1];
    attr[0].id = cudaLaunchAttributeProgrammaticStreamSerialization;
    attr[0].val.programmaticStreamSerializationAllowed = 1;
    cfg.attrs    = attr;
    cfg.numAttrs = 1;

    cudaLaunchKernelEx(&cfg, rows_kernel, hidden, b_cls, b_topic, b_token,
                       topic_inds, topic_mask, token_inds, token_mask, out);
}